// round 4
// baseline (speedup 1.0000x reference)
#include <cuda_runtime.h>

#define N_NODES 50000
#define N_EDGES 800000
#define DIM 64
#define NLAYERS 3
#define LN_EPS 1e-5f

// ---------------- device scratch (no allocations allowed) ----------------
__device__ float g_h[(size_t)N_NODES * DIM];    // per-layer GEMM output
__device__ float g_buf[(size_t)N_NODES * DIM];  // layer activations ping buffer
__device__ int   g_deg[N_NODES];
__device__ int   g_rowptr[N_NODES + 1];
__device__ int   g_cursor[N_NODES];
__device__ int   g_colidx[N_EDGES];
__device__ float g_dinv[N_NODES];

// ---------------- CSR construction ----------------
__global__ void zero_deg_kernel() {
    int i = blockIdx.x * blockDim.x + threadIdx.x;
    if (i < N_NODES) g_deg[i] = 0;
}

__global__ void hist_kernel(const int* __restrict__ dst) {
    int e = blockIdx.x * blockDim.x + threadIdx.x;
    if (e < N_EDGES) atomicAdd(&g_deg[__ldg(dst + e)], 1);
}

// Single-block exclusive scan over 50k degrees + dinv computation.
__global__ void scan_kernel() {
    __shared__ int ssum[1024];
    const int CH = (N_NODES + 1023) / 1024;  // 49
    int t = threadIdx.x;
    int base = t * CH;
    int sum = 0;
    for (int i = 0; i < CH; i++) {
        int idx = base + i;
        if (idx < N_NODES) sum += g_deg[idx];
    }
    ssum[t] = sum;
    __syncthreads();
    // Hillis-Steele inclusive scan over 1024 partials
    for (int off = 1; off < 1024; off <<= 1) {
        int v = (t >= off) ? ssum[t - off] : 0;
        __syncthreads();
        ssum[t] += v;
        __syncthreads();
    }
    int run = ssum[t] - sum;  // exclusive prefix of this chunk
    for (int i = 0; i < CH; i++) {
        int idx = base + i;
        if (idx < N_NODES) {
            int d = g_deg[idx];
            g_rowptr[idx] = run;
            g_cursor[idx] = run;
            g_dinv[idx]   = rsqrtf((float)(d + 1));  // +1 self-loop
            run += d;
        }
    }
    if (t == 0) g_rowptr[N_NODES] = N_EDGES;
}

__global__ void fill_csr_kernel(const int* __restrict__ src,
                                const int* __restrict__ dst) {
    int e = blockIdx.x * blockDim.x + threadIdx.x;
    if (e < N_EDGES) {
        int d = __ldg(dst + e);
        int pos = atomicAdd(&g_cursor[d], 1);
        g_colidx[pos] = __ldg(src + e);
    }
}

// ---------------- dense transform: g_h = X @ W ----------------
// Warp-per-row; W staged in smem; x row held as float2 per lane, broadcast via shfl.
#define ROWS_PER_WARP 4
__global__ void gemm64_kernel(const float* __restrict__ Xext, int use_ext,
                              const float* __restrict__ W) {
    __shared__ float sW[DIM * DIM];
    const float* __restrict__ X = use_ext ? Xext : (const float*)g_buf;
    int tid = threadIdx.x;
    for (int idx = tid; idx < DIM * DIM; idx += 256) sW[idx] = W[idx];
    __syncthreads();

    int lane = tid & 31;
    int warp = tid >> 5;
    int rowBase = (blockIdx.x * 8 + warp) * ROWS_PER_WARP;
    const float2* sW2 = (const float2*)sW;

    #pragma unroll
    for (int r = 0; r < ROWS_PER_WARP; r++) {
        int row = rowBase + r;
        if (row >= N_NODES) return;
        float2 xv = __ldg((const float2*)(X + (size_t)row * DIM) + lane);
        float accx = 0.f, accy = 0.f;
        #pragma unroll
        for (int k = 0; k < DIM; k++) {
            float xk = __shfl_sync(0xffffffffu, (k & 1) ? xv.y : xv.x, k >> 1);
            float2 w = sW2[k * 32 + lane];
            accx = fmaf(xk, w.x, accx);
            accy = fmaf(xk, w.y, accy);
        }
        ((float2*)(g_h + (size_t)row * DIM))[lane] = make_float2(accx, accy);
    }
}

// ---------------- fused aggregate + bias + LayerNorm + ReLU ----------------
// One warp per destination node; lane owns cols [2*lane, 2*lane+1].
__global__ void agg_ln_relu_kernel(const float* __restrict__ bias,
                                   const float* __restrict__ gamma,
                                   const float* __restrict__ beta,
                                   float* __restrict__ out_ext, int use_ext) {
    int gw = (blockIdx.x * blockDim.x + threadIdx.x) >> 5;
    int lane = threadIdx.x & 31;
    if (gw >= N_NODES) return;
    float* out = use_ext ? out_ext : g_buf;
    const float2* __restrict__ H2 = (const float2*)g_h;

    float di = g_dinv[gw];
    float2 hv = __ldg(H2 + (size_t)gw * (DIM / 2) + lane);
    float sl = di * di;  // self-loop norm
    float accx = sl * hv.x;
    float accy = sl * hv.y;

    int s0 = g_rowptr[gw];
    int s1 = g_rowptr[gw + 1];
    for (int b = s0; b < s1; b += 32) {
        int n = s1 - b;
        if (n > 32) n = 32;
        int   srcn = 0;
        float w    = 0.f;
        if (lane < n) {
            srcn = g_colidx[b + lane];
            w    = __ldg(g_dinv + srcn) * di;
        }
        // software-pipelined gather: load edge k+1 before FMA of edge k
        int   sk = __shfl_sync(0xffffffffu, srcn, 0);
        float wk = __shfl_sync(0xffffffffu, w, 0);
        float2 v = __ldg(H2 + (size_t)sk * (DIM / 2) + lane);
        for (int k = 0; k < n; k++) {
            float2 vcur = v;
            float  wcur = wk;
            if (k + 1 < n) {
                int   sn = __shfl_sync(0xffffffffu, srcn, k + 1);
                wk = __shfl_sync(0xffffffffu, w, k + 1);
                v  = __ldg(H2 + (size_t)sn * (DIM / 2) + lane);
            }
            accx = fmaf(wcur, vcur.x, accx);
            accy = fmaf(wcur, vcur.y, accy);
        }
    }

    accx += bias[2 * lane];
    accy += bias[2 * lane + 1];

    // LayerNorm over 64 features via warp reduction
    float s  = accx + accy;
    float sq = accx * accx + accy * accy;
    #pragma unroll
    for (int o = 16; o; o >>= 1) {
        s  += __shfl_xor_sync(0xffffffffu, s,  o);
        sq += __shfl_xor_sync(0xffffffffu, sq, o);
    }
    float mu   = s * (1.0f / DIM);
    float var  = sq * (1.0f / DIM) - mu * mu;
    float rstd = rsqrtf(var + LN_EPS);
    float y0 = (accx - mu) * rstd * gamma[2 * lane]     + beta[2 * lane];
    float y1 = (accy - mu) * rstd * gamma[2 * lane + 1] + beta[2 * lane + 1];
    y0 = fmaxf(y0, 0.f);
    y1 = fmaxf(y1, 0.f);
    ((float2*)(out + (size_t)gw * DIM))[lane] = make_float2(y0, y1);
}

// ---------------- launch ----------------
extern "C" void kernel_launch(void* const* d_in, const int* in_sizes, int n_in,
                              void* d_out, int out_size) {
    const float* x     = (const float*)d_in[0];
    const int*   ei    = (const int*)  d_in[1];   // [2, E] row-major
    const float* Ws    = (const float*)d_in[2];   // [3, 64, 64]
    const float* bs    = (const float*)d_in[3];   // [3, 64]
    const float* gs    = (const float*)d_in[4];   // [3, 64]
    const float* betas = (const float*)d_in[5];   // [3, 64]
    const int* srcp = ei;
    const int* dstp = ei + N_EDGES;
    float* out = (float*)d_out;

    zero_deg_kernel<<<(N_NODES + 255) / 256, 256>>>();
    hist_kernel<<<(N_EDGES + 255) / 256, 256>>>(dstp);
    scan_kernel<<<1, 1024>>>();
    fill_csr_kernel<<<(N_EDGES + 255) / 256, 256>>>(srcp, dstp);

    const int gemm_blocks = (N_NODES + 8 * ROWS_PER_WARP - 1) / (8 * ROWS_PER_WARP);
    const int agg_blocks  = (N_NODES * 32 + 255) / 256;

    for (int l = 0; l < NLAYERS; l++) {
        gemm64_kernel<<<gemm_blocks, 256>>>(x, l == 0 ? 1 : 0, Ws + l * DIM * DIM);
        agg_ln_relu_kernel<<<agg_blocks, 256>>>(bs + l * DIM, gs + l * DIM,
                                                betas + l * DIM,
                                                out, l == NLAYERS - 1 ? 1 : 0);
    }
}